// round 1
// baseline (speedup 1.0000x reference)
#include <cuda_runtime.h>
#include <math.h>
#include <stdint.h>

// Problem constants
constexpr int Bb = 4;
constexpr int Tt = 512;
constexpr int BT = Bb * Tt;          // 2048
constexpr int Dd = 768;
constexpr int Hh = 12;
constexpr int HD = 64;
constexpr int Ll = 6;
constexpr int Vv = 50257;
constexpr int VP = 50304;            // 393 * 128, padded vocab
constexpr int FF = 4 * Dd;           // 3072
constexpr float EPS = 1e-5f;
constexpr int BHT = Bb * Hh * Tt;    // rows of attention matrix

// ---------------- static scratch (no cudaMalloc allowed) ----------------
__device__ float g_x[BT * Dd];        // residual stream
__device__ float g_ln[BT * Dd];       // layernorm output
__device__ float g_h[BT * Dd];        // in_proj output
__device__ float g_q[BT * Dd];
__device__ float g_k[BT * Dd];
__device__ float g_v[BT * Dd];
__device__ float g_attn[BT * Dd];
__device__ float g_ff[BT * FF];
__device__ float g_wei[(size_t)Bb * Hh * Tt * Tt];   // attention probs
__device__ float g_wT[(size_t)Ll * 3 * Dd * Dd];     // transposed q,k,v weights
__device__ float g_wpad[(size_t)Dd * VP];            // padded out_w
__device__ float g_nll[BT];                          // per-row nll
__device__ float g_logits_fb[(size_t)BT * Vv];       // fallback if out buffer lacks logits

// ---------------- embedding ----------------
__global__ void embed_kernel(const int* __restrict__ x,
                             const float* __restrict__ tok,
                             const float* __restrict__ pos,
                             float* __restrict__ out) {
    int row = blockIdx.x;
    int id = x[row];
    int t = row % Tt;
    const float* tp = tok + (size_t)id * Dd;
    const float* pp = pos + (size_t)t * Dd;
    float* op = out + (size_t)row * Dd;
    for (int d = threadIdx.x; d < Dd; d += blockDim.x)
        op[d] = tp[d] + pp[d];
}

// ---------------- weight transpose: [L,H,D,HD] -> [L,3,D,H*HD] ----------------
__global__ void tqkv_kernel(const float* __restrict__ wq,
                            const float* __restrict__ wk,
                            const float* __restrict__ wv,
                            float* __restrict__ dst) {
    size_t total = (size_t)Ll * 3 * Dd * Dd;
    for (size_t idx = (size_t)blockIdx.x * blockDim.x + threadIdx.x;
         idx < total; idx += (size_t)gridDim.x * blockDim.x) {
        int n = (int)(idx % Dd);
        int d = (int)((idx / Dd) % Dd);
        int w = (int)((idx / ((size_t)Dd * Dd)) % 3);
        int l = (int)(idx / ((size_t)3 * Dd * Dd));
        int h = n / HD, e = n % HD;
        const float* src = (w == 0) ? wq : (w == 1) ? wk : wv;
        dst[idx] = src[(((size_t)l * Hh + h) * Dd + d) * HD + e];
    }
}

// ---------------- pad out_w: [D,V] -> [D,VP] ----------------
__global__ void padw_kernel(const float* __restrict__ w, float* __restrict__ dst) {
    size_t total = (size_t)Dd * VP;
    for (size_t idx = (size_t)blockIdx.x * blockDim.x + threadIdx.x;
         idx < total; idx += (size_t)gridDim.x * blockDim.x) {
        int n = (int)(idx % VP);
        int k = (int)(idx / VP);
        dst[idx] = (n < Vv) ? w[(size_t)k * Vv + n] : 0.f;
    }
}

// ---------------- layernorm ----------------
__global__ void ln_kernel(const float* __restrict__ in, float* __restrict__ out,
                          const float* __restrict__ g, const float* __restrict__ b) {
    int row = blockIdx.x;
    const float* x = in + (size_t)row * Dd;
    float* y = out + (size_t)row * Dd;
    int tid = threadIdx.x;
    float s = 0.f, s2 = 0.f;
    for (int d = tid; d < Dd; d += blockDim.x) {
        float v = x[d];
        s += v; s2 += v * v;
    }
    __shared__ float r1[256], r2[256];
    r1[tid] = s; r2[tid] = s2;
    __syncthreads();
    for (int off = 128; off > 0; off >>= 1) {
        if (tid < off) { r1[tid] += r1[tid + off]; r2[tid] += r2[tid + off]; }
        __syncthreads();
    }
    float mean = r1[0] * (1.f / Dd);
    float var = r2[0] * (1.f / Dd) - mean * mean;
    float rstd = rsqrtf(var + EPS);
    for (int d = tid; d < Dd; d += blockDim.x)
        y[d] = (x[d] - mean) * rstd * g[d] + b[d];
}

// ---------------- generic SGEMM: C[M,N] = A[M,K]*B[K,N](+bias)(+res)(+relu) ----------------
// BM=BN=128, BK=8, 256 threads, 8x8 per thread (split 4+4 micro tiles)
// Requires: M%128==0, K%8==0, ldb%4==0, gridDim.x*128 <= ldb (loads unguarded),
//           writes guarded by n < N.
template <bool RELU, bool RES>
__global__ void __launch_bounds__(256)
sgemm_kernel(int M, int N, int K, int ldb,
             const float* __restrict__ A, const float* __restrict__ Bm,
             const float* __restrict__ bias, const float* __restrict__ res,
             float* __restrict__ C) {
    constexpr int BK = 8;
    __shared__ float As[BK][128];
    __shared__ float Bs[BK][128];
    const int tid = threadIdx.x;
    const int tx = tid & 15;
    const int ty = tid >> 4;
    const int bm = blockIdx.y * 128;
    const int bn = blockIdx.x * 128;
    const int arow = tid >> 1;
    const int acol = (tid & 1) << 2;
    const int brow = tid >> 5;
    const int bcol = (tid & 31) << 2;
    const float* Ag = A + (size_t)(bm + arow) * K + acol;
    const float* Bg = Bm + (size_t)brow * ldb + bn + bcol;

    float acc[8][8];
#pragma unroll
    for (int i = 0; i < 8; i++)
#pragma unroll
        for (int j = 0; j < 8; j++) acc[i][j] = 0.f;

    for (int k0 = 0; k0 < K; k0 += BK) {
        float4 av = *reinterpret_cast<const float4*>(Ag + k0);
        As[acol + 0][arow] = av.x;
        As[acol + 1][arow] = av.y;
        As[acol + 2][arow] = av.z;
        As[acol + 3][arow] = av.w;
        float4 bv = *reinterpret_cast<const float4*>(Bg + (size_t)k0 * ldb);
        *reinterpret_cast<float4*>(&Bs[brow][bcol]) = bv;
        __syncthreads();
#pragma unroll
        for (int kk = 0; kk < BK; kk++) {
            float af[8], bf[8];
            *reinterpret_cast<float4*>(&af[0]) = *reinterpret_cast<const float4*>(&As[kk][ty * 4]);
            *reinterpret_cast<float4*>(&af[4]) = *reinterpret_cast<const float4*>(&As[kk][64 + ty * 4]);
            *reinterpret_cast<float4*>(&bf[0]) = *reinterpret_cast<const float4*>(&Bs[kk][tx * 4]);
            *reinterpret_cast<float4*>(&bf[4]) = *reinterpret_cast<const float4*>(&Bs[kk][64 + tx * 4]);
#pragma unroll
            for (int i = 0; i < 8; i++)
#pragma unroll
                for (int j = 0; j < 8; j++)
                    acc[i][j] = fmaf(af[i], bf[j], acc[i][j]);
        }
        __syncthreads();
    }

#pragma unroll
    for (int i = 0; i < 8; i++) {
        int m = bm + ((i < 4) ? (ty * 4 + i) : (64 + ty * 4 + i - 4));
#pragma unroll
        for (int j = 0; j < 8; j++) {
            int n = bn + ((j < 4) ? (tx * 4 + j) : (64 + tx * 4 + j - 4));
            if (n < N) {
                float v = acc[i][j] + bias[n];
                if (RES) v += res[(size_t)m * N + n];
                if (RELU) v = fmaxf(v, 0.f);
                C[(size_t)m * N + n] = v;
            }
        }
    }
}

// ---------------- attention scores: wei[b,h,t,s] = sum_e k[t,e]*q[s,e] ----------------
// grid: (s_tiles=8, t_tiles=8, B*H). 64x64 tile per block, 256 thr, 4x4/thread.
__global__ void __launch_bounds__(256)
scores_kernel(const float* __restrict__ Kmat, const float* __restrict__ Qmat,
              float* __restrict__ W) {
    int bh = blockIdx.z;
    int b = bh / Hh, h = bh % Hh;
    int t0 = blockIdx.y * 64;
    int s0 = blockIdx.x * 64;
    if (s0 > t0 + 63) return;  // fully above causal diagonal
    __shared__ float Ks[16][64];
    __shared__ float Qs[16][64];
    int tid = threadIdx.x;
    int tx = tid & 15, ty = tid >> 4;
    float acc[4][4] = {};
    const float* kb = Kmat + (size_t)b * Tt * Dd + h * HD;
    const float* qb = Qmat + (size_t)b * Tt * Dd + h * HD;
    int r = tid >> 2;
    int c4 = (tid & 3) << 2;
    for (int e0 = 0; e0 < HD; e0 += 16) {
        float4 kv = *reinterpret_cast<const float4*>(kb + (size_t)(t0 + r) * Dd + e0 + c4);
        Ks[c4 + 0][r] = kv.x; Ks[c4 + 1][r] = kv.y; Ks[c4 + 2][r] = kv.z; Ks[c4 + 3][r] = kv.w;
        float4 qv = *reinterpret_cast<const float4*>(qb + (size_t)(s0 + r) * Dd + e0 + c4);
        Qs[c4 + 0][r] = qv.x; Qs[c4 + 1][r] = qv.y; Qs[c4 + 2][r] = qv.z; Qs[c4 + 3][r] = qv.w;
        __syncthreads();
#pragma unroll
        for (int e = 0; e < 16; e++) {
            float af[4], bf[4];
            *reinterpret_cast<float4*>(af) = *reinterpret_cast<const float4*>(&Ks[e][ty * 4]);
            *reinterpret_cast<float4*>(bf) = *reinterpret_cast<const float4*>(&Qs[e][tx * 4]);
#pragma unroll
            for (int i = 0; i < 4; i++)
#pragma unroll
                for (int j = 0; j < 4; j++)
                    acc[i][j] = fmaf(af[i], bf[j], acc[i][j]);
        }
        __syncthreads();
    }
    float* wb = W + ((size_t)bh * Tt) * Tt;
#pragma unroll
    for (int i = 0; i < 4; i++) {
        int t = t0 + ty * 4 + i;
#pragma unroll
        for (int j = 0; j < 4; j++) {
            int s = s0 + tx * 4 + j;
            wb[(size_t)t * Tt + s] = acc[i][j];
        }
    }
}

// ---------------- causal softmax over s (row length t+1), zero-fill rest ----------------
__global__ void softmax_kernel(float* __restrict__ W) {
    int row = blockIdx.x;                 // bh*T + t
    int t = row % Tt;
    int n = t + 1;
    float* w = W + (size_t)row * Tt;
    int tid = threadIdx.x;                // 128
    __shared__ float red[128];
    float m = -INFINITY;
    for (int s = tid; s < n; s += 128) m = fmaxf(m, w[s]);
    red[tid] = m; __syncthreads();
    for (int off = 64; off > 0; off >>= 1) {
        if (tid < off) red[tid] = fmaxf(red[tid], red[tid + off]);
        __syncthreads();
    }
    m = red[0];
    __syncthreads();
    float sum = 0.f;
    for (int s = tid; s < n; s += 128) sum += __expf(w[s] - m);
    red[tid] = sum; __syncthreads();
    for (int off = 64; off > 0; off >>= 1) {
        if (tid < off) red[tid] += red[tid + off];
        __syncthreads();
    }
    float inv = 1.f / red[0];
    for (int s = tid; s < Tt; s += 128)
        w[s] = (s < n) ? __expf(w[s] - m) * inv : 0.f;
}

// ---------------- attn = probs @ V : out[t,e] = sum_s w[t,s]*v[s,e] ----------------
// grid: (t_tiles=8, B*H). 64(t) x 64(e) per block.
__global__ void __launch_bounds__(256)
attnv_kernel(const float* __restrict__ W, const float* __restrict__ Vmat,
             float* __restrict__ O) {
    int bh = blockIdx.y;
    int b = bh / Hh, h = bh % Hh;
    int t0 = blockIdx.x * 64;
    __shared__ float Ws[16][64];   // [s_local][t]
    __shared__ float Vs[16][64];   // [s_local][e]
    int tid = threadIdx.x;
    int tx = tid & 15, ty = tid >> 4;
    float acc[4][4] = {};
    const float* wb = W + ((size_t)bh * Tt + t0) * Tt;
    const float* vb = Vmat + (size_t)b * Tt * Dd + h * HD;
    int r = tid >> 2;
    int c4 = (tid & 3) << 2;
    int vr = tid >> 4;
    int vc = (tid & 15) << 2;
    for (int s0 = 0; s0 <= t0 + 63 && s0 < Tt; s0 += 16) {
        float4 wv = *reinterpret_cast<const float4*>(wb + (size_t)r * Tt + s0 + c4);
        Ws[c4 + 0][r] = wv.x; Ws[c4 + 1][r] = wv.y; Ws[c4 + 2][r] = wv.z; Ws[c4 + 3][r] = wv.w;
        float4 vv = *reinterpret_cast<const float4*>(vb + (size_t)(s0 + vr) * Dd + vc);
        *reinterpret_cast<float4*>(&Vs[vr][vc]) = vv;
        __syncthreads();
#pragma unroll
        for (int ss = 0; ss < 16; ss++) {
            float af[4], bf[4];
            *reinterpret_cast<float4*>(af) = *reinterpret_cast<const float4*>(&Ws[ss][ty * 4]);
            *reinterpret_cast<float4*>(bf) = *reinterpret_cast<const float4*>(&Vs[ss][tx * 4]);
#pragma unroll
            for (int i = 0; i < 4; i++)
#pragma unroll
                for (int j = 0; j < 4; j++)
                    acc[i][j] = fmaf(af[i], bf[j], acc[i][j]);
        }
        __syncthreads();
    }
#pragma unroll
    for (int i = 0; i < 4; i++) {
        int t = t0 + ty * 4 + i;
#pragma unroll
        for (int j = 0; j < 4; j++) {
            int e = tx * 4 + j;
            O[((size_t)b * Tt + t) * Dd + h * HD + e] = acc[i][j];
        }
    }
}

// ---------------- loss: per-row online logsumexp, then deterministic reduce ----------------
__global__ void nll_kernel(const float* __restrict__ logits, const int* __restrict__ target,
                           float* __restrict__ nll) {
    int row = blockIdx.x;
    const float* lg = logits + (size_t)row * Vv;
    int tid = threadIdx.x;  // 256
    float m = -INFINITY, s = 0.f;
    for (int v = tid; v < Vv; v += 256) {
        float x = lg[v];
        if (x > m) { s = s * __expf(m - x) + 1.f; m = x; }
        else s += __expf(x - m);
    }
    __shared__ float ms[256], ss[256];
    ms[tid] = m; ss[tid] = s;
    __syncthreads();
    for (int off = 128; off > 0; off >>= 1) {
        if (tid < off) {
            float m2 = ms[tid + off], s2 = ss[tid + off];
            float M = fmaxf(ms[tid], m2);
            ss[tid] = ss[tid] * __expf(ms[tid] - M) + s2 * __expf(m2 - M);
            ms[tid] = M;
        }
        __syncthreads();
    }
    if (tid == 0) {
        float lse = ms[0] + logf(ss[0]);
        nll[row] = lse - lg[target[row]];
    }
}

__global__ void loss_reduce_kernel(const float* __restrict__ nll, float* __restrict__ out) {
    __shared__ float red[256];
    int tid = threadIdx.x;
    float s = 0.f;
    for (int i = tid; i < BT; i += 256) s += nll[i];
    red[tid] = s; __syncthreads();
    for (int off = 128; off > 0; off >>= 1) {
        if (tid < off) red[tid] += red[tid + off];
        __syncthreads();
    }
    if (tid == 0) out[0] = red[0] * (1.f / BT);
}

// ---------------- host driver ----------------
extern "C" void kernel_launch(void* const* d_in, const int* in_sizes, int n_in,
                              void* d_out, int out_size) {
    const int* x      = (const int*)d_in[0];
    const int* target = (const int*)d_in[1];
    const float* tok  = (const float*)d_in[2];
    const float* pos  = (const float*)d_in[3];
    const float* ipw  = (const float*)d_in[4];
    const float* ipb  = (const float*)d_in[5];
    const float* wk   = (const float*)d_in[6];
    const float* bk   = (const float*)d_in[7];
    const float* wq   = (const float*)d_in[8];
    const float* bq   = (const float*)d_in[9];
    const float* wv   = (const float*)d_in[10];
    const float* bv   = (const float*)d_in[11];
    const float* opw  = (const float*)d_in[12];
    const float* opb  = (const float*)d_in[13];
    const float* w1   = (const float*)d_in[14];
    const float* b1   = (const float*)d_in[15];
    const float* w2   = (const float*)d_in[16];
    const float* b2   = (const float*)d_in[17];
    const float* lnag = (const float*)d_in[18];
    const float* lnab = (const float*)d_in[19];
    const float* lnfg = (const float*)d_in[20];
    const float* lnfb = (const float*)d_in[21];
    const float* outw = (const float*)d_in[22];
    const float* outb = (const float*)d_in[23];
    float* out = (float*)d_out;

    float *p_x, *p_ln, *p_h, *p_q, *p_k, *p_v, *p_attn, *p_ff, *p_wei, *p_wT, *p_wpad, *p_nll, *p_lfb;
    cudaGetSymbolAddress((void**)&p_x, g_x);
    cudaGetSymbolAddress((void**)&p_ln, g_ln);
    cudaGetSymbolAddress((void**)&p_h, g_h);
    cudaGetSymbolAddress((void**)&p_q, g_q);
    cudaGetSymbolAddress((void**)&p_k, g_k);
    cudaGetSymbolAddress((void**)&p_v, g_v);
    cudaGetSymbolAddress((void**)&p_attn, g_attn);
    cudaGetSymbolAddress((void**)&p_ff, g_ff);
    cudaGetSymbolAddress((void**)&p_wei, g_wei);
    cudaGetSymbolAddress((void**)&p_wT, g_wT);
    cudaGetSymbolAddress((void**)&p_wpad, g_wpad);
    cudaGetSymbolAddress((void**)&p_nll, g_nll);
    cudaGetSymbolAddress((void**)&p_lfb, g_logits_fb);

    const size_t BTV = (size_t)BT * Vv;
    float* logits_dst = ((size_t)out_size >= BTV) ? out : p_lfb;

    embed_kernel<<<BT, 256>>>(x, tok, pos, p_x);
    tqkv_kernel<<<4096, 256>>>(wq, wk, wv, p_wT);
    padw_kernel<<<8192, 256>>>(outw, p_wpad);

    dim3 gD(Dd / 128, BT / 128);        // (6,16)
    dim3 gF(FF / 128, BT / 128);        // (24,16)
    dim3 gV(VP / 128, BT / 128);        // (393,16)

    for (int l = 0; l < Ll; l++) {
        const float* wqt = p_wT + ((size_t)l * 3 + 0) * Dd * Dd;
        const float* wkt = p_wT + ((size_t)l * 3 + 1) * Dd * Dd;
        const float* wvt = p_wT + ((size_t)l * 3 + 2) * Dd * Dd;

        ln_kernel<<<BT, 256>>>(p_x, p_ln, lnag + (size_t)l * Dd, lnab + (size_t)l * Dd);
        sgemm_kernel<false, false><<<gD, 256>>>(BT, Dd, Dd, Dd, p_ln,
            ipw + (size_t)l * Dd * Dd, ipb + (size_t)l * Dd, nullptr, p_h);

        sgemm_kernel<false, false><<<gD, 256>>>(BT, Dd, Dd, Dd, p_h, wqt,
            bq + (size_t)l * Dd, nullptr, p_q);
        sgemm_kernel<false, false><<<gD, 256>>>(BT, Dd, Dd, Dd, p_h, wkt,
            bk + (size_t)l * Dd, nullptr, p_k);
        sgemm_kernel<false, false><<<gD, 256>>>(BT, Dd, Dd, Dd, p_h, wvt,
            bv + (size_t)l * Dd, nullptr, p_v);

        scores_kernel<<<dim3(Tt / 64, Tt / 64, Bb * Hh), 256>>>(p_k, p_q, p_wei);
        softmax_kernel<<<BHT, 128>>>(p_wei);
        attnv_kernel<<<dim3(Tt / 64, Bb * Hh), 256>>>(p_wei, p_v, p_attn);

        sgemm_kernel<false, true><<<gD, 256>>>(BT, Dd, Dd, Dd, p_attn,
            opw + (size_t)l * Dd * Dd, opb + (size_t)l * Dd, p_x, p_x);

        ln_kernel<<<BT, 256>>>(p_x, p_ln, lnfg + (size_t)l * Dd, lnfb + (size_t)l * Dd);
        sgemm_kernel<true, false><<<gF, 256>>>(BT, FF, Dd, FF, p_ln,
            w1 + (size_t)l * Dd * FF, b1 + (size_t)l * FF, nullptr, p_ff);
        sgemm_kernel<false, true><<<gD, 256>>>(BT, Dd, FF, Dd, p_ff,
            w2 + (size_t)l * FF * Dd, b2 + (size_t)l * Dd, p_x, p_x);
    }

    // final logits (no final layernorm in this model — faithful quirk)
    sgemm_kernel<false, false><<<gV, 256>>>(BT, Vv, Dd, VP, p_x, p_wpad, outb,
                                            nullptr, logits_dst);

    // loss
    nll_kernel<<<BT, 256>>>(logits_dst, target, p_nll);
    if ((size_t)out_size > BTV) {
        loss_reduce_kernel<<<1, 256>>>(p_nll, out + BTV);
    } else if (out_size == 1) {
        loss_reduce_kernel<<<1, 256>>>(p_nll, out);
    }
}

// round 2
// speedup vs baseline: 2.5508x; 2.5508x over previous
#include <cuda_runtime.h>
#include <math.h>
#include <stdint.h>

// Problem constants
constexpr int Bb = 4;
constexpr int Tt = 512;
constexpr int BT = Bb * Tt;          // 2048
constexpr int Dd = 768;
constexpr int Hh = 12;
constexpr int HD = 64;
constexpr int Ll = 6;
constexpr int Vv = 50257;
constexpr int VP = 50304;            // 393 * 128, padded vocab
constexpr int FF = 4 * Dd;           // 3072
constexpr int QS = 3 * Dd;           // 2304, fused qkv row stride
constexpr float EPS = 1e-5f;
constexpr int BHT = Bb * Hh * Tt;

// ---------------- static scratch (no cudaMalloc allowed) ----------------
__device__ float g_x[BT * Dd];
__device__ float g_ln[BT * Dd];
__device__ float g_h[BT * Dd];
__device__ float g_qkv[(size_t)BT * QS];             // fused [q|k|v]
__device__ float g_attn[BT * Dd];
__device__ float g_ff[BT * FF];
__device__ float g_wei[(size_t)Bb * Hh * Tt * Tt];
__device__ float g_wT[(size_t)Ll * Dd * QS];         // [l][d][w*768+n]
__device__ float g_bqkv[(size_t)Ll * QS];
__device__ float g_wpad[(size_t)Dd * VP];
__device__ float g_nll[BT];
__device__ float g_logits_fb[(size_t)BT * Vv];

// ---------------- embedding ----------------
__global__ void embed_kernel(const int* __restrict__ x,
                             const float* __restrict__ tok,
                             const float* __restrict__ pos,
                             float* __restrict__ out) {
    int row = blockIdx.x;
    int id = x[row];
    int t = row % Tt;
    const float* tp = tok + (size_t)id * Dd;
    const float* pp = pos + (size_t)t * Dd;
    float* op = out + (size_t)row * Dd;
    for (int d = threadIdx.x; d < Dd; d += blockDim.x)
        op[d] = tp[d] + pp[d];
}

// ---------------- weight transpose: [L,H,D,HD]x3 -> [L, D, 3*D] (q|k|v) ----------------
__global__ void tqkv_kernel(const float* __restrict__ wq,
                            const float* __restrict__ wk,
                            const float* __restrict__ wv,
                            float* __restrict__ dst) {
    size_t total = (size_t)Ll * Dd * QS;
    for (size_t idx = (size_t)blockIdx.x * blockDim.x + threadIdx.x;
         idx < total; idx += (size_t)gridDim.x * blockDim.x) {
        int n2 = (int)(idx % QS);
        int d = (int)((idx / QS) % Dd);
        int l = (int)(idx / ((size_t)QS * Dd));
        int w = n2 / Dd, n = n2 % Dd;
        int h = n / HD, e = n % HD;
        const float* src = (w == 0) ? wq : (w == 1) ? wk : wv;
        dst[idx] = src[(((size_t)l * Hh + h) * Dd + d) * HD + e];
    }
}

__global__ void bqkv_kernel(const float* __restrict__ bq,
                            const float* __restrict__ bk,
                            const float* __restrict__ bv,
                            float* __restrict__ dst) {
    int idx = blockIdx.x * blockDim.x + threadIdx.x;
    if (idx >= Ll * QS) return;
    int n2 = idx % QS, l = idx / QS;
    int w = n2 / Dd, n = n2 % Dd;
    const float* src = (w == 0) ? bq : (w == 1) ? bk : bv;
    dst[idx] = src[l * Dd + n];
}

// ---------------- pad out_w: [D,V] -> [D,VP] ----------------
__global__ void padw_kernel(const float* __restrict__ w, float* __restrict__ dst) {
    size_t total = (size_t)Dd * VP;
    for (size_t idx = (size_t)blockIdx.x * blockDim.x + threadIdx.x;
         idx < total; idx += (size_t)gridDim.x * blockDim.x) {
        int n = (int)(idx % VP);
        int k = (int)(idx / VP);
        dst[idx] = (n < Vv) ? w[(size_t)k * Vv + n] : 0.f;
    }
}

// ---------------- layernorm ----------------
__global__ void ln_kernel(const float* __restrict__ in, float* __restrict__ out,
                          const float* __restrict__ g, const float* __restrict__ b) {
    int row = blockIdx.x;
    const float* x = in + (size_t)row * Dd;
    float* y = out + (size_t)row * Dd;
    int tid = threadIdx.x;
    float s = 0.f, s2 = 0.f;
    for (int d = tid; d < Dd; d += blockDim.x) {
        float v = x[d];
        s += v; s2 += v * v;
    }
    __shared__ float r1[256], r2[256];
    r1[tid] = s; r2[tid] = s2;
    __syncthreads();
    for (int off = 128; off > 0; off >>= 1) {
        if (tid < off) { r1[tid] += r1[tid + off]; r2[tid] += r2[tid + off]; }
        __syncthreads();
    }
    float mean = r1[0] * (1.f / Dd);
    float var = r2[0] * (1.f / Dd) - mean * mean;
    float rstd = rsqrtf(var + EPS);
    for (int d = tid; d < Dd; d += blockDim.x)
        y[d] = (x[d] - mean) * rstd * g[d] + b[d];
}

// ---------------- tf32 tensor-core GEMM ----------------
// C[M,N] = A[M,K] @ B[K,N] (+bias, +res, +relu).  BM=BN=128, BK=16.
// 256 threads = 8 warps (2 M x 4 N), warp tile 64x32, mma.m16n8k8.tf32.
// Requires M%128==0, K%16==0, ldb%4==0, B padded so unguarded loads up to
// gridDim.x*128 columns are valid. Writes guarded by n < N.
constexpr int SA = 20;    // As row stride (floats) — conflict-free frag reads
constexpr int SB = 132;   // Bs row stride (floats)

__device__ __forceinline__ uint32_t f2tf32(float f) {
    uint32_t u;
    asm("cvt.rna.tf32.f32 %0, %1;" : "=r"(u) : "f"(f));
    return u;
}
__device__ __forceinline__ float4 cvt4_tf32(float4 v) {
    return make_float4(__uint_as_float(f2tf32(v.x)), __uint_as_float(f2tf32(v.y)),
                       __uint_as_float(f2tf32(v.z)), __uint_as_float(f2tf32(v.w)));
}
__device__ __forceinline__ void mma_tf32(float* c, const uint32_t* a, const uint32_t* b) {
    asm volatile(
        "mma.sync.aligned.m16n8k8.row.col.f32.tf32.tf32.f32 "
        "{%0,%1,%2,%3}, {%4,%5,%6,%7}, {%8,%9}, {%0,%1,%2,%3};"
        : "+f"(c[0]), "+f"(c[1]), "+f"(c[2]), "+f"(c[3])
        : "r"(a[0]), "r"(a[1]), "r"(a[2]), "r"(a[3]), "r"(b[0]), "r"(b[1]));
}

template <bool RELU, bool RES>
__global__ void __launch_bounds__(256)
tgemm_kernel(int M, int N, int K, int ldb,
             const float* __restrict__ A, const float* __restrict__ Bm,
             const float* __restrict__ bias, const float* __restrict__ res,
             float* __restrict__ C) {
    __shared__ float As[2][128 * SA];
    __shared__ float Bs[2][16 * SB];

    const int tid = threadIdx.x;
    const int lane = tid & 31;
    const int wid = tid >> 5;
    const int wm = wid & 1;        // 0..1
    const int wn = wid >> 1;       // 0..3
    const int bm = blockIdx.y * 128;
    const int bn = blockIdx.x * 128;

    // stage-load indexing
    const int ar0 = tid >> 1;                 // unused style; use idx math below
    (void)ar0;

    float acc[4][4][4];
#pragma unroll
    for (int i = 0; i < 4; i++)
#pragma unroll
        for (int j = 0; j < 4; j++)
#pragma unroll
            for (int k = 0; k < 4; k++) acc[i][j][k] = 0.f;

    // per-thread stage-load coordinates (2 float4 each for A and B)
    const int aIdx0 = tid, aIdx1 = tid + 256;       // over 512 = 128 rows x 4 float4
    const int ar[2] = { aIdx0 >> 2, aIdx1 >> 2 };
    const int ac[2] = { (aIdx0 & 3) << 2, (aIdx1 & 3) << 2 };
    const int br[2] = { aIdx0 >> 5, aIdx1 >> 5 };   // over 512 = 16 rows x 32 float4
    const int bc[2] = { (aIdx0 & 31) << 2, (aIdx1 & 31) << 2 };

    const float* Ab = A + (size_t)bm * K;
    const float* Bb_ = Bm + bn;

    // initial stage -> buffer 0
#pragma unroll
    for (int i = 0; i < 2; i++) {
        float4 v = *reinterpret_cast<const float4*>(Ab + (size_t)ar[i] * K + ac[i]);
        *reinterpret_cast<float4*>(&As[0][ar[i] * SA + ac[i]]) = cvt4_tf32(v);
        float4 w = *reinterpret_cast<const float4*>(Bb_ + (size_t)br[i] * ldb + bc[i]);
        *reinterpret_cast<float4*>(&Bs[0][br[i] * SB + bc[i]]) = cvt4_tf32(w);
    }
    __syncthreads();

    int buf = 0;
    for (int kt = 0; kt < K; kt += 16) {
        const bool has_next = (kt + 16) < K;
        float4 pa[2], pb[2];
        if (has_next) {
#pragma unroll
            for (int i = 0; i < 2; i++) {
                pa[i] = *reinterpret_cast<const float4*>(Ab + (size_t)ar[i] * K + kt + 16 + ac[i]);
                pb[i] = *reinterpret_cast<const float4*>(Bb_ + (size_t)(kt + 16 + br[i]) * ldb + bc[i]);
            }
        }

#pragma unroll
        for (int ks = 0; ks < 2; ks++) {
            const int kb = ks * 8;
            uint32_t a[4][4], b[4][2];
#pragma unroll
            for (int mi = 0; mi < 4; mi++) {
                const float* ap = &As[buf][(wm * 64 + mi * 16 + (lane >> 2)) * SA + kb + (lane & 3)];
                a[mi][0] = __float_as_uint(ap[0]);
                a[mi][1] = __float_as_uint(ap[8 * SA]);
                a[mi][2] = __float_as_uint(ap[4]);
                a[mi][3] = __float_as_uint(ap[8 * SA + 4]);
            }
#pragma unroll
            for (int ni = 0; ni < 4; ni++) {
                const float* bp = &Bs[buf][(kb + (lane & 3)) * SB + wn * 32 + ni * 8 + (lane >> 2)];
                b[ni][0] = __float_as_uint(bp[0]);
                b[ni][1] = __float_as_uint(bp[4 * SB]);
            }
#pragma unroll
            for (int mi = 0; mi < 4; mi++)
#pragma unroll
                for (int ni = 0; ni < 4; ni++)
                    mma_tf32(acc[mi][ni], a[mi], b[ni]);
        }

        if (has_next) {
#pragma unroll
            for (int i = 0; i < 2; i++) {
                *reinterpret_cast<float4*>(&As[buf ^ 1][ar[i] * SA + ac[i]]) = cvt4_tf32(pa[i]);
                *reinterpret_cast<float4*>(&Bs[buf ^ 1][br[i] * SB + bc[i]]) = cvt4_tf32(pb[i]);
            }
        }
        __syncthreads();
        buf ^= 1;
    }

    // epilogue
#pragma unroll
    for (int mi = 0; mi < 4; mi++) {
        const int m0 = bm + wm * 64 + mi * 16 + (lane >> 2);
#pragma unroll
        for (int ni = 0; ni < 4; ni++) {
            const int n0 = bn + wn * 32 + ni * 8 + ((lane & 3) << 1);
            const float* c = acc[mi][ni];
#pragma unroll
            for (int half = 0; half < 2; half++) {
                const int m = m0 + half * 8;
                float v0 = c[half * 2 + 0];
                float v1 = c[half * 2 + 1];
                if (n0 < N) {
                    float v = v0 + bias[n0];
                    if (RES) v += res[(size_t)m * N + n0];
                    if (RELU) v = fmaxf(v, 0.f);
                    C[(size_t)m * N + n0] = v;
                }
                if (n0 + 1 < N) {
                    float v = v1 + bias[n0 + 1];
                    if (RES) v += res[(size_t)m * N + n0 + 1];
                    if (RELU) v = fmaxf(v, 0.f);
                    C[(size_t)m * N + n0 + 1] = v;
                }
            }
        }
    }
}

// ---------------- attention scores: wei[b,h,t,s] = sum_e k[t,e]*q[s,e] ----------------
__global__ void __launch_bounds__(256)
scores_kernel(const float* __restrict__ QKV, float* __restrict__ W) {
    int bh = blockIdx.z;
    int b = bh / Hh, h = bh % Hh;
    int t0 = blockIdx.y * 64;
    int s0 = blockIdx.x * 64;
    if (s0 > t0 + 63) return;
    __shared__ float Ks[16][64];
    __shared__ float Qs[16][64];
    int tid = threadIdx.x;
    int tx = tid & 15, ty = tid >> 4;
    float acc[4][4] = {};
    const float* kb = QKV + (size_t)b * Tt * QS + Dd + h * HD;      // k at offset D
    const float* qb = QKV + (size_t)b * Tt * QS + h * HD;           // q at offset 0
    int r = tid >> 2;
    int c4 = (tid & 3) << 2;
    for (int e0 = 0; e0 < HD; e0 += 16) {
        float4 kv = *reinterpret_cast<const float4*>(kb + (size_t)(t0 + r) * QS + e0 + c4);
        Ks[c4 + 0][r] = kv.x; Ks[c4 + 1][r] = kv.y; Ks[c4 + 2][r] = kv.z; Ks[c4 + 3][r] = kv.w;
        float4 qv = *reinterpret_cast<const float4*>(qb + (size_t)(s0 + r) * QS + e0 + c4);
        Qs[c4 + 0][r] = qv.x; Qs[c4 + 1][r] = qv.y; Qs[c4 + 2][r] = qv.z; Qs[c4 + 3][r] = qv.w;
        __syncthreads();
#pragma unroll
        for (int e = 0; e < 16; e++) {
            float af[4], bf[4];
            *reinterpret_cast<float4*>(af) = *reinterpret_cast<const float4*>(&Ks[e][ty * 4]);
            *reinterpret_cast<float4*>(bf) = *reinterpret_cast<const float4*>(&Qs[e][tx * 4]);
#pragma unroll
            for (int i = 0; i < 4; i++)
#pragma unroll
                for (int j = 0; j < 4; j++)
                    acc[i][j] = fmaf(af[i], bf[j], acc[i][j]);
        }
        __syncthreads();
    }
    float* wb = W + ((size_t)bh * Tt) * Tt;
#pragma unroll
    for (int i = 0; i < 4; i++) {
        int t = t0 + ty * 4 + i;
#pragma unroll
        for (int j = 0; j < 4; j++) {
            int s = s0 + tx * 4 + j;
            wb[(size_t)t * Tt + s] = acc[i][j];
        }
    }
}

// ---------------- causal softmax ----------------
__global__ void softmax_kernel(float* __restrict__ W) {
    int row = blockIdx.x;
    int t = row % Tt;
    int n = t + 1;
    float* w = W + (size_t)row * Tt;
    int tid = threadIdx.x;
    __shared__ float red[128];
    float m = -INFINITY;
    for (int s = tid; s < n; s += 128) m = fmaxf(m, w[s]);
    red[tid] = m; __syncthreads();
    for (int off = 64; off > 0; off >>= 1) {
        if (tid < off) red[tid] = fmaxf(red[tid], red[tid + off]);
        __syncthreads();
    }
    m = red[0];
    __syncthreads();
    float sum = 0.f;
    for (int s = tid; s < n; s += 128) sum += __expf(w[s] - m);
    red[tid] = sum; __syncthreads();
    for (int off = 64; off > 0; off >>= 1) {
        if (tid < off) red[tid] += red[tid + off];
        __syncthreads();
    }
    float inv = 1.f / red[0];
    for (int s = tid; s < Tt; s += 128)
        w[s] = (s < n) ? __expf(w[s] - m) * inv : 0.f;
}

// ---------------- attn = probs @ V ----------------
__global__ void __launch_bounds__(256)
attnv_kernel(const float* __restrict__ W, const float* __restrict__ QKV,
             float* __restrict__ O) {
    int bh = blockIdx.y;
    int b = bh / Hh, h = bh % Hh;
    int t0 = blockIdx.x * 64;
    __shared__ float Ws[16][64];
    __shared__ float Vs[16][64];
    int tid = threadIdx.x;
    int tx = tid & 15, ty = tid >> 4;
    float acc[4][4] = {};
    const float* wb = W + ((size_t)bh * Tt + t0) * Tt;
    const float* vb = QKV + (size_t)b * Tt * QS + 2 * Dd + h * HD;  // v at offset 2D
    int r = tid >> 2;
    int c4 = (tid & 3) << 2;
    int vr = tid >> 4;
    int vc = (tid & 15) << 2;
    for (int s0 = 0; s0 <= t0 + 63 && s0 < Tt; s0 += 16) {
        float4 wv = *reinterpret_cast<const float4*>(wb + (size_t)r * Tt + s0 + c4);
        Ws[c4 + 0][r] = wv.x; Ws[c4 + 1][r] = wv.y; Ws[c4 + 2][r] = wv.z; Ws[c4 + 3][r] = wv.w;
        float4 vv = *reinterpret_cast<const float4*>(vb + (size_t)(s0 + vr) * QS + vc);
        *reinterpret_cast<float4*>(&Vs[vr][vc]) = vv;
        __syncthreads();
#pragma unroll
        for (int ss = 0; ss < 16; ss++) {
            float af[4], bf[4];
            *reinterpret_cast<float4*>(af) = *reinterpret_cast<const float4*>(&Ws[ss][ty * 4]);
            *reinterpret_cast<float4*>(bf) = *reinterpret_cast<const float4*>(&Vs[ss][tx * 4]);
#pragma unroll
            for (int i = 0; i < 4; i++)
#pragma unroll
                for (int j = 0; j < 4; j++)
                    acc[i][j] = fmaf(af[i], bf[j], acc[i][j]);
        }
        __syncthreads();
    }
#pragma unroll
    for (int i = 0; i < 4; i++) {
        int t = t0 + ty * 4 + i;
#pragma unroll
        for (int j = 0; j < 4; j++) {
            int e = tx * 4 + j;
            O[((size_t)b * Tt + t) * Dd + h * HD + e] = acc[i][j];
        }
    }
}

// ---------------- loss ----------------
__global__ void nll_kernel(const float* __restrict__ logits, const int* __restrict__ target,
                           float* __restrict__ nll) {
    int row = blockIdx.x;
    const float* lg = logits + (size_t)row * Vv;
    int tid = threadIdx.x;
    float m = -INFINITY, s = 0.f;
    for (int v = tid; v < Vv; v += 256) {
        float x = lg[v];
        if (x > m) { s = s * __expf(m - x) + 1.f; m = x; }
        else s += __expf(x - m);
    }
    __shared__ float ms[256], ss[256];
    ms[tid] = m; ss[tid] = s;
    __syncthreads();
    for (int off = 128; off > 0; off >>= 1) {
        if (tid < off) {
            float m2 = ms[tid + off], s2 = ss[tid + off];
            float M = fmaxf(ms[tid], m2);
            ss[tid] = ss[tid] * __expf(ms[tid] - M) + s2 * __expf(m2 - M);
            ms[tid] = M;
        }
        __syncthreads();
    }
    if (tid == 0) {
        float lse = ms[0] + logf(ss[0]);
        nll[row] = lse - lg[target[row]];
    }
}

__global__ void loss_reduce_kernel(const float* __restrict__ nll, float* __restrict__ out) {
    __shared__ float red[256];
    int tid = threadIdx.x;
    float s = 0.f;
    for (int i = tid; i < BT; i += 256) s += nll[i];
    red[tid] = s; __syncthreads();
    for (int off = 128; off > 0; off >>= 1) {
        if (tid < off) red[tid] += red[tid + off];
        __syncthreads();
    }
    if (tid == 0) out[0] = red[0] * (1.f / BT);
}

// ---------------- host driver ----------------
extern "C" void kernel_launch(void* const* d_in, const int* in_sizes, int n_in,
                              void* d_out, int out_size) {
    const int* x      = (const int*)d_in[0];
    const int* target = (const int*)d_in[1];
    const float* tok  = (const float*)d_in[2];
    const float* pos  = (const float*)d_in[3];
    const float* ipw  = (const float*)d_in[4];
    const float* ipb  = (const float*)d_in[5];
    const float* wk   = (const float*)d_in[6];
    const float* bk   = (const float*)d_in[7];
    const float* wq   = (const float*)d_in[8];
    const float* bq   = (const float*)d_in[9];
    const float* wv   = (const float*)d_in[10];
    const float* bv   = (const float*)d_in[11];
    const float* opw  = (const float*)d_in[12];
    const float* opb  = (const float*)d_in[13];
    const float* w1   = (const float*)d_in[14];
    const float* b1   = (const float*)d_in[15];
    const float* w2   = (const float*)d_in[16];
    const float* b2   = (const float*)d_in[17];
    const float* lnag = (const float*)d_in[18];
    const float* lnab = (const float*)d_in[19];
    const float* lnfg = (const float*)d_in[20];
    const float* lnfb = (const float*)d_in[21];
    const float* outw = (const float*)d_in[22];
    const float* outb = (const float*)d_in[23];
    float* out = (float*)d_out;

    float *p_x, *p_ln, *p_h, *p_qkv, *p_attn, *p_ff, *p_wei, *p_wT, *p_bqkv,
          *p_wpad, *p_nll, *p_lfb;
    cudaGetSymbolAddress((void**)&p_x, g_x);
    cudaGetSymbolAddress((void**)&p_ln, g_ln);
    cudaGetSymbolAddress((void**)&p_h, g_h);
    cudaGetSymbolAddress((void**)&p_qkv, g_qkv);
    cudaGetSymbolAddress((void**)&p_attn, g_attn);
    cudaGetSymbolAddress((void**)&p_ff, g_ff);
    cudaGetSymbolAddress((void**)&p_wei, g_wei);
    cudaGetSymbolAddress((void**)&p_wT, g_wT);
    cudaGetSymbolAddress((void**)&p_bqkv, g_bqkv);
    cudaGetSymbolAddress((void**)&p_wpad, g_wpad);
    cudaGetSymbolAddress((void**)&p_nll, g_nll);
    cudaGetSymbolAddress((void**)&p_lfb, g_logits_fb);

    const size_t BTV = (size_t)BT * Vv;
    float* logits_dst = ((size_t)out_size >= BTV) ? out : p_lfb;

    embed_kernel<<<BT, 256>>>(x, tok, pos, p_x);
    tqkv_kernel<<<4096, 256>>>(wq, wk, wv, p_wT);
    bqkv_kernel<<<(Ll * QS + 255) / 256, 256>>>(bq, bk, bv, p_bqkv);
    padw_kernel<<<8192, 256>>>(outw, p_wpad);

    dim3 gD(Dd / 128, BT / 128);        // (6,16)
    dim3 gQ(QS / 128, BT / 128);        // (18,16)
    dim3 gF(FF / 128, BT / 128);        // (24,16)
    dim3 gV(VP / 128, BT / 128);        // (393,16)

    for (int l = 0; l < Ll; l++) {
        ln_kernel<<<BT, 256>>>(p_x, p_ln, lnag + (size_t)l * Dd, lnab + (size_t)l * Dd);
        tgemm_kernel<false, false><<<gD, 256>>>(BT, Dd, Dd, Dd, p_ln,
            ipw + (size_t)l * Dd * Dd, ipb + (size_t)l * Dd, nullptr, p_h);

        tgemm_kernel<false, false><<<gQ, 256>>>(BT, QS, Dd, QS, p_h,
            p_wT + (size_t)l * Dd * QS, p_bqkv + (size_t)l * QS, nullptr, p_qkv);

        scores_kernel<<<dim3(Tt / 64, Tt / 64, Bb * Hh), 256>>>(p_qkv, p_wei);
        softmax_kernel<<<BHT, 128>>>(p_wei);
        attnv_kernel<<<dim3(Tt / 64, Bb * Hh), 256>>>(p_wei, p_qkv, p_attn);

        tgemm_kernel<false, true><<<gD, 256>>>(BT, Dd, Dd, Dd, p_attn,
            opw + (size_t)l * Dd * Dd, opb + (size_t)l * Dd, p_x, p_x);

        ln_kernel<<<BT, 256>>>(p_x, p_ln, lnfg + (size_t)l * Dd, lnfb + (size_t)l * Dd);
        tgemm_kernel<true, false><<<gF, 256>>>(BT, FF, Dd, FF, p_ln,
            w1 + (size_t)l * Dd * FF, b1 + (size_t)l * FF, nullptr, p_ff);
        tgemm_kernel<false, true><<<gD, 256>>>(BT, Dd, FF, Dd, p_ff,
            w2 + (size_t)l * FF * Dd, b2 + (size_t)l * Dd, p_x, p_x);
    }

    tgemm_kernel<false, false><<<gV, 256>>>(BT, Vv, Dd, VP, p_x, p_wpad, outb,
                                            nullptr, logits_dst);

    nll_kernel<<<BT, 256>>>(logits_dst, target, p_nll);
    if ((size_t)out_size > BTV) {
        loss_reduce_kernel<<<1, 256>>>(p_nll, out + BTV);
    } else if (out_size == 1) {
        loss_reduce_kernel<<<1, 256>>>(p_nll, out);
    }
}

// round 3
// speedup vs baseline: 2.6747x; 1.0485x over previous
#include <cuda_runtime.h>
#include <math.h>
#include <stdint.h>

// Problem constants
constexpr int Bb = 4;
constexpr int Tt = 512;
constexpr int BT = Bb * Tt;          // 2048
constexpr int Dd = 768;
constexpr int Hh = 12;
constexpr int HD = 64;
constexpr int Ll = 6;
constexpr int Vv = 50257;
constexpr int VP = 50304;            // 393 * 128, padded vocab
constexpr int FF = 4 * Dd;           // 3072
constexpr int QS = 3 * Dd;           // 2304, fused qkv row stride
constexpr float EPS = 1e-5f;

// ---------------- static scratch ----------------
__device__ float g_x[BT * Dd];
__device__ float g_ln[BT * Dd];
__device__ float g_h[BT * Dd];
__device__ float g_qkv[(size_t)BT * QS];
__device__ float g_attn[BT * Dd];
__device__ float g_ff[BT * FF];
__device__ float g_wT[(size_t)Ll * Dd * QS];
__device__ float g_bqkv[(size_t)Ll * QS];
__device__ float g_wpad[(size_t)Dd * VP];
__device__ float g_nll[BT];
__device__ float g_logits_fb[(size_t)BT * Vv];

// ---------------- embedding ----------------
__global__ void embed_kernel(const int* __restrict__ x,
                             const float* __restrict__ tok,
                             const float* __restrict__ pos,
                             float* __restrict__ out) {
    int row = blockIdx.x;
    int id = x[row];
    int t = row % Tt;
    const float* tp = tok + (size_t)id * Dd;
    const float* pp = pos + (size_t)t * Dd;
    float* op = out + (size_t)row * Dd;
    for (int d = threadIdx.x; d < Dd; d += blockDim.x)
        op[d] = tp[d] + pp[d];
}

// ---------------- weight transpose: [L,H,D,HD]x3 -> [L, D, 3*D] ----------------
__global__ void tqkv_kernel(const float* __restrict__ wq,
                            const float* __restrict__ wk,
                            const float* __restrict__ wv,
                            float* __restrict__ dst) {
    size_t total = (size_t)Ll * Dd * QS;
    for (size_t idx = (size_t)blockIdx.x * blockDim.x + threadIdx.x;
         idx < total; idx += (size_t)gridDim.x * blockDim.x) {
        int n2 = (int)(idx % QS);
        int d = (int)((idx / QS) % Dd);
        int l = (int)(idx / ((size_t)QS * Dd));
        int w = n2 / Dd, n = n2 % Dd;
        int h = n / HD, e = n % HD;
        const float* src = (w == 0) ? wq : (w == 1) ? wk : wv;
        dst[idx] = src[(((size_t)l * Hh + h) * Dd + d) * HD + e];
    }
}

__global__ void bqkv_kernel(const float* __restrict__ bq,
                            const float* __restrict__ bk,
                            const float* __restrict__ bv,
                            float* __restrict__ dst) {
    int idx = blockIdx.x * blockDim.x + threadIdx.x;
    if (idx >= Ll * QS) return;
    int n2 = idx % QS, l = idx / QS;
    int w = n2 / Dd, n = n2 % Dd;
    const float* src = (w == 0) ? bq : (w == 1) ? bk : bv;
    dst[idx] = src[l * Dd + n];
}

// ---------------- pad out_w: [D,V] -> [D,VP] ----------------
__global__ void padw_kernel(const float* __restrict__ w, float* __restrict__ dst) {
    size_t total = (size_t)Dd * VP;
    for (size_t idx = (size_t)blockIdx.x * blockDim.x + threadIdx.x;
         idx < total; idx += (size_t)gridDim.x * blockDim.x) {
        int n = (int)(idx % VP);
        int k = (int)(idx / VP);
        dst[idx] = (n < Vv) ? w[(size_t)k * Vv + n] : 0.f;
    }
}

// ---------------- layernorm: warp per row, x cached in regs ----------------
__global__ void __launch_bounds__(256)
ln_kernel(const float* __restrict__ in, float* __restrict__ out,
          const float* __restrict__ g, const float* __restrict__ b) {
    const int warp = threadIdx.x >> 5;
    const int lane = threadIdx.x & 31;
    const int row = blockIdx.x * 8 + warp;
    const float* x = in + (size_t)row * Dd;
    float4 v[6];
    float s = 0.f, s2 = 0.f;
#pragma unroll
    for (int i = 0; i < 6; i++) {
        v[i] = *reinterpret_cast<const float4*>(x + i * 128 + lane * 4);
        s += v[i].x + v[i].y + v[i].z + v[i].w;
        s2 += v[i].x * v[i].x + v[i].y * v[i].y + v[i].z * v[i].z + v[i].w * v[i].w;
    }
#pragma unroll
    for (int off = 16; off > 0; off >>= 1) {
        s += __shfl_xor_sync(0xffffffffu, s, off);
        s2 += __shfl_xor_sync(0xffffffffu, s2, off);
    }
    float mean = s * (1.f / Dd);
    float var = s2 * (1.f / Dd) - mean * mean;
    float rstd = rsqrtf(var + EPS);
    float* y = out + (size_t)row * Dd;
#pragma unroll
    for (int i = 0; i < 6; i++) {
        float4 gg = *reinterpret_cast<const float4*>(g + i * 128 + lane * 4);
        float4 bb = *reinterpret_cast<const float4*>(b + i * 128 + lane * 4);
        float4 w;
        w.x = (v[i].x - mean) * rstd * gg.x + bb.x;
        w.y = (v[i].y - mean) * rstd * gg.y + bb.y;
        w.z = (v[i].z - mean) * rstd * gg.z + bb.z;
        w.w = (v[i].w - mean) * rstd * gg.w + bb.w;
        *reinterpret_cast<float4*>(y + i * 128 + lane * 4) = w;
    }
}

// ---------------- tf32 tensor-core GEMM v2 ----------------
// 128 threads = 4 warps (2M x 2N), warp tile 64 x (BN/2), mma m16n8k8.
// BM=128, BK=16. Same K accumulation order as before.
constexpr int SA = 20;

__device__ __forceinline__ uint32_t f2tf32(float f) {
    uint32_t u;
    asm("cvt.rna.tf32.f32 %0, %1;" : "=r"(u) : "f"(f));
    return u;
}
__device__ __forceinline__ float4 cvt4_tf32(float4 v) {
    return make_float4(__uint_as_float(f2tf32(v.x)), __uint_as_float(f2tf32(v.y)),
                       __uint_as_float(f2tf32(v.z)), __uint_as_float(f2tf32(v.w)));
}
__device__ __forceinline__ void mma_tf32(float* c, const uint32_t* a, const uint32_t* b) {
    asm volatile(
        "mma.sync.aligned.m16n8k8.row.col.f32.tf32.tf32.f32 "
        "{%0,%1,%2,%3}, {%4,%5,%6,%7}, {%8,%9}, {%0,%1,%2,%3};"
        : "+f"(c[0]), "+f"(c[1]), "+f"(c[2]), "+f"(c[3])
        : "r"(a[0]), "r"(a[1]), "r"(a[2]), "r"(a[3]), "r"(b[0]), "r"(b[1]));
}

template <int BN, bool RELU, bool RES>
__global__ void __launch_bounds__(128)
tgemm_kernel(int M, int N, int K, int ldb,
             const float* __restrict__ A, const float* __restrict__ Bm,
             const float* __restrict__ bias, const float* __restrict__ res,
             float* __restrict__ C) {
    constexpr int NI = BN / 16;          // n8 mma count per warp
    constexpr int SBp = BN + 4;
    constexpr int NB = BN / 32;          // B float4 loads per thread
    __shared__ float As[2][128 * SA];
    __shared__ float Bs[2][16 * SBp];

    const int tid = threadIdx.x;
    const int lane = tid & 31;
    const int wid = tid >> 5;
    const int wm = wid & 1;
    const int wn = wid >> 1;
    const int bm = blockIdx.y * 128;
    const int bn = blockIdx.x * BN;

    float acc[4][NI][4];
#pragma unroll
    for (int i = 0; i < 4; i++)
#pragma unroll
        for (int j = 0; j < NI; j++)
#pragma unroll
            for (int k = 0; k < 4; k++) acc[i][j][k] = 0.f;

    int ar[4], ac[4];
#pragma unroll
    for (int i = 0; i < 4; i++) {
        int idx = tid + i * 128;
        ar[i] = idx >> 2;
        ac[i] = (idx & 3) << 2;
    }
    int br[NB], bc[NB];
#pragma unroll
    for (int i = 0; i < NB; i++) {
        int idx = tid + i * 128;
        br[i] = idx / (BN / 4);
        bc[i] = (idx % (BN / 4)) << 2;
    }

    const float* Ab = A + (size_t)bm * K;
    const float* Bb_ = Bm + bn;

#pragma unroll
    for (int i = 0; i < 4; i++) {
        float4 v = *reinterpret_cast<const float4*>(Ab + (size_t)ar[i] * K + ac[i]);
        *reinterpret_cast<float4*>(&As[0][ar[i] * SA + ac[i]]) = cvt4_tf32(v);
    }
#pragma unroll
    for (int i = 0; i < NB; i++) {
        float4 w = *reinterpret_cast<const float4*>(Bb_ + (size_t)br[i] * ldb + bc[i]);
        *reinterpret_cast<float4*>(&Bs[0][br[i] * SBp + bc[i]]) = cvt4_tf32(w);
    }
    __syncthreads();

    int buf = 0;
    for (int kt = 0; kt < K; kt += 16) {
        const bool has_next = (kt + 16) < K;
        float4 pa[4], pb[NB];
        if (has_next) {
#pragma unroll
            for (int i = 0; i < 4; i++)
                pa[i] = *reinterpret_cast<const float4*>(Ab + (size_t)ar[i] * K + kt + 16 + ac[i]);
#pragma unroll
            for (int i = 0; i < NB; i++)
                pb[i] = *reinterpret_cast<const float4*>(Bb_ + (size_t)(kt + 16 + br[i]) * ldb + bc[i]);
        }

#pragma unroll
        for (int ks = 0; ks < 2; ks++) {
            const int kb = ks * 8;
            uint32_t a[4][4], b[NI][2];
#pragma unroll
            for (int mi = 0; mi < 4; mi++) {
                const float* ap = &As[buf][(wm * 64 + mi * 16 + (lane >> 2)) * SA + kb + (lane & 3)];
                a[mi][0] = __float_as_uint(ap[0]);
                a[mi][1] = __float_as_uint(ap[8 * SA]);
                a[mi][2] = __float_as_uint(ap[4]);
                a[mi][3] = __float_as_uint(ap[8 * SA + 4]);
            }
#pragma unroll
            for (int ni = 0; ni < NI; ni++) {
                const float* bp = &Bs[buf][(kb + (lane & 3)) * SBp + wn * (BN / 2) + ni * 8 + (lane >> 2)];
                b[ni][0] = __float_as_uint(bp[0]);
                b[ni][1] = __float_as_uint(bp[4 * SBp]);
            }
#pragma unroll
            for (int mi = 0; mi < 4; mi++)
#pragma unroll
                for (int ni = 0; ni < NI; ni++)
                    mma_tf32(acc[mi][ni], a[mi], b[ni]);
        }

        if (has_next) {
#pragma unroll
            for (int i = 0; i < 4; i++)
                *reinterpret_cast<float4*>(&As[buf ^ 1][ar[i] * SA + ac[i]]) = cvt4_tf32(pa[i]);
#pragma unroll
            for (int i = 0; i < NB; i++)
                *reinterpret_cast<float4*>(&Bs[buf ^ 1][br[i] * SBp + bc[i]]) = cvt4_tf32(pb[i]);
        }
        __syncthreads();
        buf ^= 1;
    }

#pragma unroll
    for (int mi = 0; mi < 4; mi++) {
        const int m0 = bm + wm * 64 + mi * 16 + (lane >> 2);
#pragma unroll
        for (int ni = 0; ni < NI; ni++) {
            const int n0 = bn + wn * (BN / 2) + ni * 8 + ((lane & 3) << 1);
            const float* c = acc[mi][ni];
#pragma unroll
            for (int half = 0; half < 2; half++) {
                const int m = m0 + half * 8;
                if (n0 < N) {
                    float v = c[half * 2 + 0] + bias[n0];
                    if (RES) v += res[(size_t)m * N + n0];
                    if (RELU) v = fmaxf(v, 0.f);
                    C[(size_t)m * N + n0] = v;
                }
                if (n0 + 1 < N) {
                    float v = c[half * 2 + 1] + bias[n0 + 1];
                    if (RES) v += res[(size_t)m * N + n0 + 1];
                    if (RELU) v = fmaxf(v, 0.f);
                    C[(size_t)m * N + n0 + 1] = v;
                }
            }
        }
    }
}

// ---------------- fused flash attention (fp32) ----------------
// wei[t,s] = k[t]·q[s], causal in (t,s), softmax over s, O = P @ V.
// Block: one (b,h) x 64 t-rows. 256 thr as 16x16, 4x4 per thread.
__global__ void __launch_bounds__(256)
flash_kernel(const float* __restrict__ QKV, float* __restrict__ O) {
    int bh = blockIdx.y;
    int b = bh / Hh, h = bh % Hh;
    int t0 = blockIdx.x * 64;
    __shared__ float Ks[16][64];
    __shared__ float Qs[16][64];
    __shared__ float Vs[16][64];
    __shared__ float Ps[64][68];
    const int tid = threadIdx.x;
    const int tx = tid & 15, ty = tid >> 4;
    const float* qb = QKV + (size_t)b * Tt * QS + h * HD;
    const float* kb = qb + Dd;
    const float* vb = qb + 2 * Dd;
    const int r = tid >> 2;
    const int c4 = (tid & 3) << 2;
    const int vr = tid >> 4;
    const int vc = (tid & 15) << 2;

    float m[4], l[4], o[4][4];
#pragma unroll
    for (int i = 0; i < 4; i++) {
        m[i] = -INFINITY; l[i] = 0.f;
#pragma unroll
        for (int j = 0; j < 4; j++) o[i][j] = 0.f;
    }

    for (int s0 = 0; s0 <= t0; s0 += 64) {
        // ---- S = K_tile @ Q_tile^T over e=0..63 ----
        float acc[4][4];
#pragma unroll
        for (int i = 0; i < 4; i++)
#pragma unroll
            for (int j = 0; j < 4; j++) acc[i][j] = 0.f;

        for (int e0 = 0; e0 < HD; e0 += 16) {
            float4 kv = *reinterpret_cast<const float4*>(kb + (size_t)(t0 + r) * QS + e0 + c4);
            Ks[c4 + 0][r] = kv.x; Ks[c4 + 1][r] = kv.y; Ks[c4 + 2][r] = kv.z; Ks[c4 + 3][r] = kv.w;
            float4 qv = *reinterpret_cast<const float4*>(qb + (size_t)(s0 + r) * QS + e0 + c4);
            Qs[c4 + 0][r] = qv.x; Qs[c4 + 1][r] = qv.y; Qs[c4 + 2][r] = qv.z; Qs[c4 + 3][r] = qv.w;
            __syncthreads();
#pragma unroll
            for (int e = 0; e < 16; e++) {
                float af[4], bf[4];
                *reinterpret_cast<float4*>(af) = *reinterpret_cast<const float4*>(&Ks[e][ty * 4]);
                *reinterpret_cast<float4*>(bf) = *reinterpret_cast<const float4*>(&Qs[e][tx * 4]);
#pragma unroll
                for (int i = 0; i < 4; i++)
#pragma unroll
                    for (int j = 0; j < 4; j++)
                        acc[i][j] = fmaf(af[i], bf[j], acc[i][j]);
            }
            __syncthreads();
        }

        // ---- causal mask (diagonal tile only) ----
        if (s0 == t0) {
#pragma unroll
            for (int i = 0; i < 4; i++)
#pragma unroll
                for (int j = 0; j < 4; j++)
                    if (tx * 4 + j > ty * 4 + i) acc[i][j] = -INFINITY;
        }

        // ---- online softmax update ----
        float p[4][4];
#pragma unroll
        for (int i = 0; i < 4; i++) {
            float mt = fmaxf(fmaxf(acc[i][0], acc[i][1]), fmaxf(acc[i][2], acc[i][3]));
#pragma unroll
            for (int off = 8; off > 0; off >>= 1)
                mt = fmaxf(mt, __shfl_xor_sync(0xffffffffu, mt, off));
            float mn = fmaxf(m[i], mt);
            float sc = __expf(m[i] - mn);
            float ls = 0.f;
#pragma unroll
            for (int j = 0; j < 4; j++) {
                p[i][j] = __expf(acc[i][j] - mn);
                ls += p[i][j];
            }
#pragma unroll
            for (int off = 8; off > 0; off >>= 1)
                ls += __shfl_xor_sync(0xffffffffu, ls, off);
            l[i] = l[i] * sc + ls;
            m[i] = mn;
#pragma unroll
            for (int j = 0; j < 4; j++) o[i][j] *= sc;
        }
#pragma unroll
        for (int i = 0; i < 4; i++)
            *reinterpret_cast<float4*>(&Ps[ty * 4 + i][tx * 4]) =
                make_float4(p[i][0], p[i][1], p[i][2], p[i][3]);
        __syncthreads();

        // ---- O += P @ V ----
        for (int ss0 = 0; ss0 < 64; ss0 += 16) {
            float4 vv = *reinterpret_cast<const float4*>(vb + (size_t)(s0 + ss0 + vr) * QS + vc);
            *reinterpret_cast<float4*>(&Vs[vr][vc]) = vv;
            __syncthreads();
#pragma unroll
            for (int ss = 0; ss < 16; ss++) {
                float bf[4];
                *reinterpret_cast<float4*>(bf) = *reinterpret_cast<const float4*>(&Vs[ss][tx * 4]);
#pragma unroll
                for (int i = 0; i < 4; i++) {
                    float a = Ps[ty * 4 + i][ss0 + ss];
#pragma unroll
                    for (int j = 0; j < 4; j++)
                        o[i][j] = fmaf(a, bf[j], o[i][j]);
                }
            }
            __syncthreads();
        }
    }

#pragma unroll
    for (int i = 0; i < 4; i++) {
        float inv = 1.f / l[i];
        float4 w = make_float4(o[i][0] * inv, o[i][1] * inv, o[i][2] * inv, o[i][3] * inv);
        *reinterpret_cast<float4*>(O + ((size_t)b * Tt + t0 + ty * 4 + i) * Dd + h * HD + tx * 4) = w;
    }
}

// ---------------- loss ----------------
__global__ void nll_kernel(const float* __restrict__ logits, const int* __restrict__ target,
                           float* __restrict__ nll) {
    int row = blockIdx.x;
    const float* lg = logits + (size_t)row * Vv;
    int tid = threadIdx.x;
    float m = -INFINITY, s = 0.f;
    for (int v = tid; v < Vv; v += 256) {
        float x = lg[v];
        if (x > m) { s = s * __expf(m - x) + 1.f; m = x; }
        else s += __expf(x - m);
    }
    __shared__ float ms[256], ss[256];
    ms[tid] = m; ss[tid] = s;
    __syncthreads();
    for (int off = 128; off > 0; off >>= 1) {
        if (tid < off) {
            float m2 = ms[tid + off], s2 = ss[tid + off];
            float M = fmaxf(ms[tid], m2);
            ss[tid] = ss[tid] * __expf(ms[tid] - M) + s2 * __expf(m2 - M);
            ms[tid] = M;
        }
        __syncthreads();
    }
    if (tid == 0) {
        float lse = ms[0] + logf(ss[0]);
        nll[row] = lse - lg[target[row]];
    }
}

__global__ void loss_reduce_kernel(const float* __restrict__ nll, float* __restrict__ out) {
    __shared__ float red[256];
    int tid = threadIdx.x;
    float s = 0.f;
    for (int i = tid; i < BT; i += 256) s += nll[i];
    red[tid] = s; __syncthreads();
    for (int off = 128; off > 0; off >>= 1) {
        if (tid < off) red[tid] += red[tid + off];
        __syncthreads();
    }
    if (tid == 0) out[0] = red[0] * (1.f / BT);
}

// ---------------- host driver ----------------
extern "C" void kernel_launch(void* const* d_in, const int* in_sizes, int n_in,
                              void* d_out, int out_size) {
    const int* x      = (const int*)d_in[0];
    const int* target = (const int*)d_in[1];
    const float* tok  = (const float*)d_in[2];
    const float* pos  = (const float*)d_in[3];
    const float* ipw  = (const float*)d_in[4];
    const float* ipb  = (const float*)d_in[5];
    const float* wk   = (const float*)d_in[6];
    const float* bk   = (const float*)d_in[7];
    const float* wq   = (const float*)d_in[8];
    const float* bq   = (const float*)d_in[9];
    const float* wv   = (const float*)d_in[10];
    const float* bv   = (const float*)d_in[11];
    const float* opw  = (const float*)d_in[12];
    const float* opb  = (const float*)d_in[13];
    const float* w1   = (const float*)d_in[14];
    const float* b1   = (const float*)d_in[15];
    const float* w2   = (const float*)d_in[16];
    const float* b2   = (const float*)d_in[17];
    const float* lnag = (const float*)d_in[18];
    const float* lnab = (const float*)d_in[19];
    const float* lnfg = (const float*)d_in[20];
    const float* lnfb = (const float*)d_in[21];
    const float* outw = (const float*)d_in[22];
    const float* outb = (const float*)d_in[23];
    float* out = (float*)d_out;

    float *p_x, *p_ln, *p_h, *p_qkv, *p_attn, *p_ff, *p_wT, *p_bqkv,
          *p_wpad, *p_nll, *p_lfb;
    cudaGetSymbolAddress((void**)&p_x, g_x);
    cudaGetSymbolAddress((void**)&p_ln, g_ln);
    cudaGetSymbolAddress((void**)&p_h, g_h);
    cudaGetSymbolAddress((void**)&p_qkv, g_qkv);
    cudaGetSymbolAddress((void**)&p_attn, g_attn);
    cudaGetSymbolAddress((void**)&p_ff, g_ff);
    cudaGetSymbolAddress((void**)&p_wT, g_wT);
    cudaGetSymbolAddress((void**)&p_bqkv, g_bqkv);
    cudaGetSymbolAddress((void**)&p_wpad, g_wpad);
    cudaGetSymbolAddress((void**)&p_nll, g_nll);
    cudaGetSymbolAddress((void**)&p_lfb, g_logits_fb);

    const size_t BTV = (size_t)BT * Vv;
    float* logits_dst = ((size_t)out_size >= BTV) ? out : p_lfb;

    embed_kernel<<<BT, 256>>>(x, tok, pos, p_x);
    tqkv_kernel<<<4096, 256>>>(wq, wk, wv, p_wT);
    bqkv_kernel<<<(Ll * QS + 255) / 256, 256>>>(bq, bk, bv, p_bqkv);
    padw_kernel<<<8192, 256>>>(outw, p_wpad);

    dim3 gD(Dd / 64, BT / 128);         // (12,16) BN=64
    dim3 gQ(QS / 128, BT / 128);        // (18,16)
    dim3 gF(FF / 128, BT / 128);        // (24,16)
    dim3 gV(VP / 128, BT / 128);        // (393,16)

    for (int l = 0; l < Ll; l++) {
        ln_kernel<<<BT / 8, 256>>>(p_x, p_ln, lnag + (size_t)l * Dd, lnab + (size_t)l * Dd);
        tgemm_kernel<64, false, false><<<gD, 128>>>(BT, Dd, Dd, Dd, p_ln,
            ipw + (size_t)l * Dd * Dd, ipb + (size_t)l * Dd, nullptr, p_h);

        tgemm_kernel<128, false, false><<<gQ, 128>>>(BT, QS, Dd, QS, p_h,
            p_wT + (size_t)l * Dd * QS, p_bqkv + (size_t)l * QS, nullptr, p_qkv);

        flash_kernel<<<dim3(Tt / 64, Bb * Hh), 256>>>(p_qkv, p_attn);

        tgemm_kernel<64, false, true><<<gD, 128>>>(BT, Dd, Dd, Dd, p_attn,
            opw + (size_t)l * Dd * Dd, opb + (size_t)l * Dd, p_x, p_x);

        ln_kernel<<<BT / 8, 256>>>(p_x, p_ln, lnfg + (size_t)l * Dd, lnfb + (size_t)l * Dd);
        tgemm_kernel<128, true, false><<<gF, 128>>>(BT, FF, Dd, FF, p_ln,
            w1 + (size_t)l * Dd * FF, b1 + (size_t)l * FF, nullptr, p_ff);
        tgemm_kernel<64, false, true><<<gD, 128>>>(BT, Dd, FF, Dd, p_ff,
            w2 + (size_t)l * FF * Dd, b2 + (size_t)l * Dd, p_x, p_x);
    }

    tgemm_kernel<128, false, false><<<gV, 128>>>(BT, Vv, Dd, VP, p_x, p_wpad, outb,
                                                 nullptr, logits_dst);

    nll_kernel<<<BT, 256>>>(logits_dst, target, p_nll);
    if ((size_t)out_size > BTV) {
        loss_reduce_kernel<<<1, 256>>>(p_nll, out + BTV);
    } else if (out_size == 1) {
        loss_reduce_kernel<<<1, 256>>>(p_nll, out);
    }
}